// round 12
// baseline (speedup 1.0000x reference)
#include <cuda_runtime.h>

// RC timing on 200k independent 16-pin trees — lane-per-pin shuffle version.
//
// One LANE per pin; each warp holds 2 nets (lanes 0-15 = net A, 16-31 = net B).
// All state in registers; ZERO shared memory, zero barriers.
//   - global loads/stores are naturally coalesced (warp = 128B contiguous)
//   - top-down path sums (delay, beta): pointer-doubling via SHFL.IDX, 4 steps
//   - bottom-up subtree sums (load, ldelay): 15-step descending broadcast
//     (node s is final when broadcast since its children s'>s were already
//     scattered), 3 cap modes pipelined per step
//   - wire-cap children-sum: same broadcast loop, dependency-free
// fa_local[i] in [0,i); root has fa=self => res=0 and pointer-doubling
// self-loop terminates naturally (root delay/beta = 0).
//
// Output: out[(metric*3 + mode)*nPins + pin].

#define TPB 256

__global__ void __launch_bounds__(TPB, 6)
rct_kernel(const float* __restrict__ x, const float* __restrict__ y,
           const int* __restrict__ fa,
           const float* __restrict__ c0, const float* __restrict__ c1,
           const float* __restrict__ c2,
           float* __restrict__ out, int nNets, int nPins)
{
    const unsigned FULL = 0xffffffffu;
    const int lane = threadIdx.x & 31;
    const int gw   = blockIdx.x * (TPB >> 5) + (threadIdx.x >> 5); // global warp
    const int nb   = gw * 2;                        // first net of this warp
    if (nb >= nNets) return;                        // warp-uniform exit

    const int  gp  = nb * 16 + lane;                // my global pin
    const bool act = (nb + (lane >> 4)) < nNets;    // my net valid?
    const int  gpc = act ? gp : (nb * 16 + (lane & 15));  // clamped (safe) pin
    const int  hb  = lane & 16;                     // half-warp base

    // ---- geometry -----------------------------------------------------------
    const float xx = __ldcs(x + gpc);
    const float yy = __ldcs(y + gpc);
    const int   fl = __ldcs(fa + gpc) - (gpc - (lane & 15));  // fa_local [0,16)
    const int   plane = hb | fl;                    // parent lane (root: self)

    const float xp = __shfl_sync(FULL, xx, plane);
    const float yp = __shfl_sync(FULL, yy, plane);
    const float res = (fabsf(xx - xp) + fabsf(yy - yp)) * 5.0e-5f; // root: 0

    // wire cap: own half-edge + children half-edges (dependency-free loop)
    float nc = res;
#pragma unroll
    for (int s = 1; s < 16; s++) {
        const int src = hb | s;
        const float rv = __shfl_sync(FULL, res, src);
        const int   pf = __shfl_sync(FULL, plane, src);
        if (lane == pf) nc += rv;
    }

    // ---- pin caps (metric 0) ------------------------------------------------
    float pc[3];
    pc[0] = __ldcs(c0 + gpc) + nc;
    pc[1] = __ldcs(c1 + gpc) + nc;
    pc[2] = __ldcs(c2 + gpc) + nc;
#pragma unroll
    for (int m = 0; m < 3; m++)
        if (act) __stcs(out + (size_t)(0 * 3 + m) * nPins + gp, pc[m]);

    // ---- LOAD: bottom-up subtree sum of pin_cap -----------------------------
    float ld[3] = { pc[0], pc[1], pc[2] };
#pragma unroll
    for (int s = 15; s >= 1; s--) {
        const int src = hb | s;
        const float v0 = __shfl_sync(FULL, ld[0], src);
        const float v1 = __shfl_sync(FULL, ld[1], src);
        const float v2 = __shfl_sync(FULL, ld[2], src);
        const int   pf = __shfl_sync(FULL, plane, src);
        if (lane == pf) { ld[0] += v0; ld[1] += v1; ld[2] += v2; }
    }
#pragma unroll
    for (int m = 0; m < 3; m++)
        if (act) __stcs(out + (size_t)(1 * 3 + m) * nPins + gp, ld[m]);

    // ---- DELAY: pointer-doubling path sum of res*load -----------------------
    float dl[3] = { res * ld[0], res * ld[1], res * ld[2] };   // root: 0
    {
        int p = plane;
#pragma unroll
        for (int j = 0; j < 4; j++) {                // 2^4 = 16 >= max path
            const float a0 = __shfl_sync(FULL, dl[0], p);
            const float a1 = __shfl_sync(FULL, dl[1], p);
            const float a2 = __shfl_sync(FULL, dl[2], p);
            dl[0] += a0; dl[1] += a1; dl[2] += a2;
            p = __shfl_sync(FULL, p, p);
        }
    }
#pragma unroll
    for (int m = 0; m < 3; m++)
        if (act) __stcs(out + (size_t)(2 * 3 + m) * nPins + gp, dl[m]);

    // ---- LDELAY: bottom-up subtree sum of pc*delay --------------------------
    float le[3] = { pc[0] * dl[0], pc[1] * dl[1], pc[2] * dl[2] };
#pragma unroll
    for (int s = 15; s >= 1; s--) {
        const int src = hb | s;
        const float v0 = __shfl_sync(FULL, le[0], src);
        const float v1 = __shfl_sync(FULL, le[1], src);
        const float v2 = __shfl_sync(FULL, le[2], src);
        const int   pf = __shfl_sync(FULL, plane, src);
        if (lane == pf) { le[0] += v0; le[1] += v1; le[2] += v2; }
    }
#pragma unroll
    for (int m = 0; m < 3; m++)
        if (act) __stcs(out + (size_t)(3 * 3 + m) * nPins + gp, le[m]);

    // ---- BETA: pointer-doubling path sum of res*ldelay ----------------------
    float be[3] = { res * le[0], res * le[1], res * le[2] };   // root: 0
    {
        int p = plane;
#pragma unroll
        for (int j = 0; j < 4; j++) {
            const float a0 = __shfl_sync(FULL, be[0], p);
            const float a1 = __shfl_sync(FULL, be[1], p);
            const float a2 = __shfl_sync(FULL, be[2], p);
            be[0] += a0; be[1] += a1; be[2] += a2;
            p = __shfl_sync(FULL, p, p);
        }
    }
#pragma unroll
    for (int m = 0; m < 3; m++)
        if (act) __stcs(out + (size_t)(4 * 3 + m) * nPins + gp, be[m]);

    // ---- IMPULSE = sqrt(max(2*beta - delay^2, 1e-12)) -----------------------
#pragma unroll
    for (int m = 0; m < 3; m++) {
        float q2 = fmaf(-dl[m], dl[m], be[m] + be[m]);
        q2 = fmaxf(q2, 1.0e-12f);
        const float im = q2 * rsqrtf(q2);            // sqrt via MUFU.RSQ
        if (act) __stcs(out + (size_t)(5 * 3 + m) * nPins + gp, im);
    }
}

extern "C" void kernel_launch(void* const* d_in, const int* in_sizes, int n_in,
                              void* d_out, int out_size)
{
    const float* x  = (const float*)d_in[0];
    const float* y  = (const float*)d_in[1];
    const int*   fa = (const int*)  d_in[4];
    const float* c0 = (const float*)d_in[8];
    const float* c1 = (const float*)d_in[9];
    const float* c2 = (const float*)d_in[10];

    const int nPins = in_sizes[0];
    const int nNets = in_sizes[3] - 1;   // net_flat_topo_sort_start has nNets+1

    const int netsPerBlock = (TPB / 32) * 2;   // 16
    const int grid = (nNets + netsPerBlock - 1) / netsPerBlock;
    rct_kernel<<<grid, TPB>>>(x, y, fa, c0, c1, c2, (float*)d_out, nNets, nPins);
}

// round 13
// speedup vs baseline: 1.1370x; 1.1370x over previous
#include <cuda_runtime.h>

// RC timing on 200k independent 16-pin trees — mode-per-thread, block-level
// geometry dedup, coalesced IO via swizzled staging, and producer/consumer
// NAMED barriers for phase desynchronization.
//
// Block = 192 threads = 6 warps = 2 independent net-groups x 3 modes; lane =
// net. fa_local[i] in [0,i) => single-sweep bottom-up / top-down recurrences
// via lane-transposed shared scratch [slot][lane] (bank == lane, no
// conflicts). Mode-0 warps compute geometry (res, wire caps, parents) once
// per net, publish via shared, then bar.arrive (no wait). Modes 1/2 prefetch
// their cap tiles into registers BEFORE bar.sync so the DRAM latency hides
// under the wait. Global I/O is warp-coalesced through per-warp staging with
// swizzle P(n,k) = 4n + ((k+n+(n>>1)) & 3) (conflict-free both phases).
//
// Output: out[(metric*3 + mode)*nPins + pin].

#define NS       16
#define TPB      192
#define NETS_PB  64

__device__ __forceinline__ int swz(int n, int k) {
    return 4 * n + ((k + n + (n >> 1)) & 3);
}

// Warp-coalesced load of 16 floats/thread (thread n = lane owns chunk 4n..4n+3).
__device__ __forceinline__ void ld16w(float4* St, const float4* wb, int lane,
                                      bool full, bool act, float* dst)
{
    if (full) {
        float4 t0 = __ldg(wb + lane),      t1 = __ldg(wb + 32 + lane),
               t2 = __ldg(wb + 64 + lane), t3 = __ldg(wb + 96 + lane);
        St[swz(lane >> 2, lane & 3)] = t0;
        { int c = 32 + lane; St[swz(c >> 2, c & 3)] = t1; }
        { int c = 64 + lane; St[swz(c >> 2, c & 3)] = t2; }
        { int c = 96 + lane; St[swz(c >> 2, c & 3)] = t3; }
        __syncwarp();
#pragma unroll
        for (int k = 0; k < 4; k++) {
            float4 v = St[swz(lane, k)];
            dst[4*k] = v.x; dst[4*k+1] = v.y; dst[4*k+2] = v.z; dst[4*k+3] = v.w;
        }
    } else if (act) {
#pragma unroll
        for (int k = 0; k < 4; k++) {
            float4 v = __ldg(wb + 4 * lane + k);
            dst[4*k] = v.x; dst[4*k+1] = v.y; dst[4*k+2] = v.z; dst[4*k+3] = v.w;
        }
    } else {
#pragma unroll
        for (int i = 0; i < NS; i++) dst[i] = 0.0f;
    }
}

// Warp-coalesced store of 16 floats/thread.
__device__ __forceinline__ void st16w(float4* St, float4* wb, int lane,
                                      bool full, bool act, const float* a)
{
    if (full) {
#pragma unroll
        for (int k = 0; k < 4; k++)
            St[swz(lane, k)] = make_float4(a[4*k], a[4*k+1], a[4*k+2], a[4*k+3]);
        __syncwarp();
#pragma unroll
        for (int j = 0; j < 4; j++) {
            int c = j * 32 + lane;
            __stcs(wb + c, St[swz(c >> 2, c & 3)]);
        }
    } else if (act) {
#pragma unroll
        for (int k = 0; k < 4; k++)
            __stcs(wb + 4 * lane + k,
                   make_float4(a[4*k], a[4*k+1], a[4*k+2], a[4*k+3]));
    }
}

__global__ void __launch_bounds__(TPB, 4)
rct_kernel(const float* __restrict__ x, const float* __restrict__ y,
           const int* __restrict__ fa,
           const float* __restrict__ c0, const float* __restrict__ c1,
           const float* __restrict__ c2,
           float* __restrict__ out, int nNets, int nPins)
{
    __shared__ float4 Stg[6 * 2 * 128];  // per-warp ping-pong staging, 24 KB
    __shared__ float  Wsm[6 * 512];      // per-warp sweep scratch, 12 KB
    __shared__ float  RNsm[2 * 1024];    // per-group (x,y)->(res,nc) fl2, 8 KB
    __shared__ int2   Fsm[2 * 32];       // per-group packed parent nibbles

    const int wib  = threadIdx.x >> 5;   // 0..5
    const int lane = threadIdx.x & 31;
    const int mode = wib % 3;
    const int grp  = wib / 3;            // 0..1
    const int netbase = blockIdx.x * NETS_PB + grp * 32;
    const int t    = netbase + lane;     // net id
    const bool act = (t < nNets);
    const bool full = (netbase + 32 <= nNets);  // warp-uniform
    const int g    = t * NS;

    float4* S0 = Stg + wib * 256;               // two 128-float4 buffers
    float*  W  = Wsm  + wib * 512 + lane;       // [slot][lane] column
    float*  RN = RNsm + grp * 1024 + lane * 2;  // float2 column
    int2*   F2 = Fsm  + grp * 32 + lane;

    const float* cb = (mode == 0) ? c0 : ((mode == 1) ? c1 : c2);
    const float4* cbv = (const float4*)cb + (size_t)netbase * 4;

    // ---- consumer cap prefetch (hides DRAM latency under the barrier) -----
    float4 p0, p1, p2, p3;
    if (mode != 0) {
        if (full) {
            p0 = __ldg(cbv + lane);      p1 = __ldg(cbv + 32 + lane);
            p2 = __ldg(cbv + 64 + lane); p3 = __ldg(cbv + 96 + lane);
        } else if (act) {
            p0 = __ldg(cbv + 4*lane + 0); p1 = __ldg(cbv + 4*lane + 1);
            p2 = __ldg(cbv + 4*lane + 2); p3 = __ldg(cbv + 4*lane + 3);
        }
    }

    int   foff[NS];                      // parent slot * 32 (element offset)
    float res[NS];
    int   ph = 0;                        // staging ping-pong phase

    // ---- geometry (mode-0 warps): res, nc, parents once per net -----------
    if (mode == 0) {
        {
            float flf[NS];
            ld16w(S0 + (ph++ & 1) * 128, (const float4*)fa + (size_t)netbase * 4,
                  lane, full, act, flf);
            unsigned pk0 = 0, pk1 = 0;
#pragma unroll
            for (int i = 0; i < NS; i++) {
                int s = act ? (__float_as_int(flf[i]) - g) : 0;
                foff[i] = s * 32;
                if (i < 8) pk0 |= (unsigned)s << (i * 4);
                else       pk1 |= (unsigned)s << ((i - 8) * 4);
            }
            *F2 = make_int2((int)pk0, (int)pk1);
        }
        float xr[NS], yr[NS];
        ld16w(S0 + (ph++ & 1) * 128, (const float4*)x + (size_t)netbase * 4,
              lane, full, act, xr);
        ld16w(S0 + (ph++ & 1) * 128, (const float4*)y + (size_t)netbase * 4,
              lane, full, act, yr);
#pragma unroll
        for (int i = 0; i < NS; i++)
            *(float2*)(RN + i * 64) = make_float2(xr[i], yr[i]);
        res[0] = 0.0f;
#pragma unroll
        for (int i = 1; i < NS; i++) {
            float2 p = *(const float2*)(RN + foff[i] * 2);
            res[i] = (fabsf(xr[i] - p.x) + fabsf(yr[i] - p.y)) * 5.0e-5f;
        }
        // wire caps: scatter half-edge caps up one level (own W region)
        W[0] = 0.0f;
#pragma unroll
        for (int i = 1; i < NS; i++) W[i * 32] = res[i];
#pragma unroll
        for (int i = NS - 1; i >= 1; i--) W[foff[i]] += res[i];
        // publish (res, nc) — overwrites xy staging (all reads done)
#pragma unroll
        for (int i = 0; i < NS; i++)
            *(float2*)(RN + i * 64) = make_float2(res[i], W[i * 32]);

        __threadfence_block();
        asm volatile("bar.arrive %0, %1;" :: "r"(grp + 1), "r"(96));
    } else {
        asm volatile("bar.sync %0, %1;" :: "r"(grp + 1), "r"(96) : "memory");
    }

    // ---- caps into registers ----------------------------------------------
    float cr[NS];
    if (mode != 0) {
        if (full) {
            float4* St = S0;
            St[swz(lane >> 2, lane & 3)] = p0;
            { int c = 32 + lane; St[swz(c >> 2, c & 3)] = p1; }
            { int c = 64 + lane; St[swz(c >> 2, c & 3)] = p2; }
            { int c = 96 + lane; St[swz(c >> 2, c & 3)] = p3; }
            __syncwarp();
#pragma unroll
            for (int k = 0; k < 4; k++) {
                float4 v = St[swz(lane, k)];
                cr[4*k] = v.x; cr[4*k+1] = v.y; cr[4*k+2] = v.z; cr[4*k+3] = v.w;
            }
        } else if (act) {
            cr[0]=p0.x; cr[1]=p0.y; cr[2]=p0.z; cr[3]=p0.w;
            cr[4]=p1.x; cr[5]=p1.y; cr[6]=p1.z; cr[7]=p1.w;
            cr[8]=p2.x; cr[9]=p2.y; cr[10]=p2.z; cr[11]=p2.w;
            cr[12]=p3.x; cr[13]=p3.y; cr[14]=p3.z; cr[15]=p3.w;
        } else {
#pragma unroll
            for (int i = 0; i < NS; i++) cr[i] = 0.0f;
        }
        ph = 1;                          // next staging use -> buffer 1
    } else {
        ld16w(S0 + (ph++ & 1) * 128, cbv, lane, full, act, cr);
    }

    // ---- uniform readback: parents + (res, nc); pc folded in --------------
    {
        int2 pk = *F2;
        unsigned pk0 = (unsigned)pk.x, pk1 = (unsigned)pk.y;
#pragma unroll
        for (int i = 0; i < 8; i++)  foff[i] = (int)((pk0 >> (i * 4)) & 15u) * 32;
#pragma unroll
        for (int i = 8; i < NS; i++) foff[i] = (int)((pk1 >> ((i - 8) * 4)) & 15u) * 32;
    }
    float u[NS], v[NS];          // u: pc -> ldelay -> beta ; v: load -> delay
#pragma unroll
    for (int i = 0; i < NS; i++) {
        float2 rn = *(const float2*)(RN + i * 64);
        res[i] = rn.x;
        u[i]   = cr[i] + rn.y;   // pc = base cap + wire cap
    }

#define OB(metric) ((float4*)out + (size_t)((metric) * 3 + mode) * (nPins >> 2) \
                    + (size_t)netbase * 4)

    st16w(S0 + (ph++ & 1) * 128, OB(0), lane, full, act, u);

    // ---- load: bottom-up subtree sum of pin_cap ---------------------------
#pragma unroll
    for (int i = 0; i < NS - 1; i++) W[i * 32] = u[i];   // slot 15 stays in reg
    v[NS - 1] = u[NS - 1];
    W[foff[NS - 1]] += v[NS - 1];
#pragma unroll
    for (int i = NS - 2; i >= 1; i--) {
        v[i] = W[i * 32];                                // descendants done
        W[foff[i]] += v[i];
    }
    v[0] = W[0];
    st16w(S0 + (ph++ & 1) * 128, OB(1), lane, full, act, v);

    // ---- delay: top-down path sum; v: load -> delay -----------------------
    W[0] = 0.0f;
    v[0] = 0.0f;                                         // root delay = 0
#pragma unroll
    for (int i = 1; i < NS; i++) {
        float pd = W[foff[i]];                           // parent = delay
        float d  = fmaf(res[i], v[i], pd);
        if (i < NS - 1) W[i * 32] = d;                   // 15 never a parent
        v[i] = d;
    }
    st16w(S0 + (ph++ & 1) * 128, OB(2), lane, full, act, v);

    // ---- ldelay: bottom-up subtree sum of pc*delay; u: pc -> ldelay -------
#pragma unroll
    for (int i = 0; i < NS - 1; i++) W[i * 32] = u[i] * v[i];
    u[NS - 1] = u[NS - 1] * v[NS - 1];
    W[foff[NS - 1]] += u[NS - 1];
#pragma unroll
    for (int i = NS - 2; i >= 1; i--) {
        u[i] = W[i * 32];
        W[foff[i]] += u[i];
    }
    u[0] = W[0];
    st16w(S0 + (ph++ & 1) * 128, OB(3), lane, full, act, u);

    // ---- beta: top-down path sum; u: ldelay -> beta -----------------------
    W[0] = 0.0f;
    u[0] = 0.0f;                                         // root beta = 0
#pragma unroll
    for (int i = 1; i < NS; i++) {
        float pb = W[foff[i]];
        float b  = fmaf(res[i], u[i], pb);
        if (i < NS - 1) W[i * 32] = b;
        u[i] = b;
    }
    st16w(S0 + (ph++ & 1) * 128, OB(4), lane, full, act, u);

    // ---- impulse = sqrt(max(2*beta - delay^2, 1e-12)) ---------------------
    {
        float im[NS];
        im[0] = 1.0e-6f;
#pragma unroll
        for (int i = 1; i < NS; i++) {
            float q2 = fmaf(-v[i], v[i], u[i] + u[i]);
            q2 = fmaxf(q2, 1.0e-12f);
            im[i] = q2 * rsqrtf(q2);                     // sqrt via MUFU.RSQ
        }
        st16w(S0 + (ph++ & 1) * 128, OB(5), lane, full, act, im);
    }
#undef OB
}

extern "C" void kernel_launch(void* const* d_in, const int* in_sizes, int n_in,
                              void* d_out, int out_size)
{
    const float* x  = (const float*)d_in[0];
    const float* y  = (const float*)d_in[1];
    const int*   fa = (const int*)  d_in[4];
    const float* c0 = (const float*)d_in[8];
    const float* c1 = (const float*)d_in[9];
    const float* c2 = (const float*)d_in[10];

    const int nPins = in_sizes[0];
    const int nNets = in_sizes[3] - 1;   // net_flat_topo_sort_start has nNets+1

    const int grid = (nNets + NETS_PB - 1) / NETS_PB;
    rct_kernel<<<grid, TPB>>>(x, y, fa, c0, c1, c2, (float*)d_out, nNets, nPins);
}